// round 10
// baseline (speedup 1.0000x reference)
#include <cuda_runtime.h>
#include <cstdint>
#include <math.h>

// ---------------- problem constants ----------------
#define BATCH   16
#define NTOK    1024
#define CIN     256
#define INNER   512
#define CTXN    77
#define CTXD    768
#define MTOK    (BATCH*NTOK)  // 16384
#define MCTX    (BATCH*CTXN)  // 1232

// rounded-weight scratch offsets
#define OFF_WIN  0
#define OFF_SAQ  131072
#define OFF_SAK  393216
#define OFF_SAV  655360
#define OFF_SAP  917504
#define OFF_CAQ  1179648
#define OFF_CAK  1441792
#define OFF_CAV  1835008
#define OFF_CAO  2228224
#define OFF_WOUT 2490368
#define WTOT     2621440

// ---------------- scratch (device globals; no allocation) ----------------
__device__ float g_gn1[MTOK*CIN];
__device__ float g_h  [MTOK*INNER];
__device__ float g_hn [MTOK*INNER];
__device__ float g_q  [MTOK*INNER];
__device__ float g_k  [MTOK*INNER];
__device__ float g_v  [MTOK*INNER];      // SA: vT [B][512][1024]; later CA: v2t [128][64][96]
__device__ float g_sim[16777216];        // SA: B*N*N; CA: [128][1024][96]
__device__ float g_o  [MTOK*INNER];
__device__ float g_k2 [MCTX*INNER];
__device__ float g_wr [WTOT];            // pre-rounded weights

// ---------------- tf32 helpers ----------------
__device__ __forceinline__ uint32_t f2tf32(float f) {
    uint32_t r;
    asm("cvt.rna.tf32.f32 %0, %1;" : "=r"(r) : "f"(f));
    return r;
}
__device__ __forceinline__ float rtf(float f) { return __uint_as_float(f2tf32(f)); }

__device__ __forceinline__ void cp16(uint32_t dst, const float* src) {
    asm volatile("cp.async.cg.shared.global [%0], [%1], 16;" :: "r"(dst), "l"(src));
}
__device__ __forceinline__ uint32_t smem_u32(const void* p) {
    uint32_t a;
    asm("{ .reg .u64 t; cvta.to.shared.u64 t, %1; cvt.u32.u64 %0, t; }" : "=r"(a) : "l"(p));
    return a;
}
__device__ __forceinline__ void mma_tf32(float* c, const uint32_t* a, const uint32_t* b) {
    asm volatile("mma.sync.aligned.m16n8k8.row.col.f32.tf32.tf32.f32 "
                 "{%0,%1,%2,%3}, {%4,%5,%6,%7}, {%8,%9}, {%0,%1,%2,%3};"
                 : "+f"(c[0]), "+f"(c[1]), "+f"(c[2]), "+f"(c[3])
                 : "r"(a[0]), "r"(a[1]), "r"(a[2]), "r"(a[3]), "r"(b[0]), "r"(b[1]));
}

// ---------------- weight pre-rounding ----------------
__global__ void wround_kernel(const float* __restrict__ w0, const float* __restrict__ w1,
                              const float* __restrict__ w2, const float* __restrict__ w3,
                              const float* __restrict__ w4, const float* __restrict__ w5,
                              const float* __restrict__ w6, const float* __restrict__ w7,
                              const float* __restrict__ w8, const float* __restrict__ w9,
                              float* __restrict__ dst)
{
    int i = blockIdx.x * 1024 + threadIdx.x;
    const float* s; int off;
    if      (i < OFF_SAQ)  { s = w0; off = OFF_WIN;  }
    else if (i < OFF_SAK)  { s = w1; off = OFF_SAQ;  }
    else if (i < OFF_SAV)  { s = w2; off = OFF_SAK;  }
    else if (i < OFF_SAP)  { s = w3; off = OFF_SAV;  }
    else if (i < OFF_CAQ)  { s = w4; off = OFF_SAP;  }
    else if (i < OFF_CAK)  { s = w5; off = OFF_CAQ;  }
    else if (i < OFF_CAV)  { s = w6; off = OFF_CAK;  }
    else if (i < OFF_CAO)  { s = w7; off = OFF_CAV;  }
    else if (i < OFF_WOUT) { s = w8; off = OFF_CAO;  }
    else                   { s = w9; off = OFF_WOUT; }
    dst[i] = rtf(s[i - off]);
}

// ---------------- GroupNorm 1 (single pass via smem cache; rounded store) ----------------
__global__ void gn1_kernel(const float* __restrict__ x, const float* __restrict__ gam,
                           const float* __restrict__ bet, float* __restrict__ out)
{
    extern __shared__ float cache[];
    int bg = blockIdx.x;
    int b  = bg >> 5, grp = bg & 31;
    const float* xb = x + ((long)b*CIN + grp*8) * NTOK;
    __shared__ float r1[256], r2[256];
    int t = threadIdx.x;
    float s = 0.f, s2 = 0.f;
    for (int i = t; i < 8192; i += 256) {
        float v = xb[i]; cache[i] = v; s += v; s2 += v*v;
    }
    r1[t] = s; r2[t] = s2; __syncthreads();
    for (int o = 128; o > 0; o >>= 1) {
        if (t < o) { r1[t] += r1[t+o]; r2[t] += r2[t+o]; }
        __syncthreads();
    }
    float mean = r1[0] * (1.f/8192.f);
    float var  = r2[0] * (1.f/8192.f) - mean*mean;
    float rstd = rsqrtf(var + 1e-5f);
    for (int i = t; i < 8192; i += 256) {
        int c = grp*8 + (i >> 10);
        int n = i & 1023;
        float v = (cache[i] - mean) * rstd * gam[c] + bet[c];
        out[((long)b*NTOK + n)*CIN + c] = rtf(v);
    }
}

// ---------------- GroupNorm 2 (single pass via smem cache; rounded store) ----------------
__global__ void gn2_kernel(const float* __restrict__ h, const float* __restrict__ gam,
                           const float* __restrict__ bet, float* __restrict__ out)
{
    extern __shared__ float cache[];
    int bg = blockIdx.x;
    int b  = bg >> 5, grp = bg & 31;
    const float* hb = h + (long)b*NTOK*INNER;
    float* ob = out + (long)b*NTOK*INNER;
    __shared__ float r1[256], r2[256];
    int t = threadIdx.x;
    float s = 0.f, s2 = 0.f;
    for (int i = t; i < 16384; i += 256) {
        int n = i >> 4, c = grp*16 + (i & 15);
        float v = hb[n*INNER + c];
        cache[i] = v; s += v; s2 += v*v;
    }
    r1[t] = s; r2[t] = s2; __syncthreads();
    for (int o = 128; o > 0; o >>= 1) {
        if (t < o) { r1[t] += r1[t+o]; r2[t] += r2[t+o]; }
        __syncthreads();
    }
    float mean = r1[0] * (1.f/16384.f);
    float var  = r2[0] * (1.f/16384.f) - mean*mean;
    float rstd = rsqrtf(var + 1e-5f);
    for (int i = t; i < 16384; i += 256) {
        int n = i >> 4, c = grp*16 + (i & 15);
        ob[n*INNER + c] = rtf((cache[i] - mean) * rstd * gam[c] + bet[c]);
    }
}

// ---------------- SA row softmax: 16384 rows x 1024 (rounded store) ----------------
__global__ void softmax_rows(float* __restrict__ S)
{
    long long row = blockIdx.x;
    float* p = S + row * 1024;
    __shared__ float red[256];
    int t = threadIdx.x;
    float v[4];
    float mx = -1e30f;
    #pragma unroll
    for (int i = 0; i < 4; i++) { v[i] = p[t + i*256]; mx = fmaxf(mx, v[i]); }
    red[t] = mx; __syncthreads();
    for (int o = 128; o > 0; o >>= 1) {
        if (t < o) red[t] = fmaxf(red[t], red[t+o]);
        __syncthreads();
    }
    mx = red[0]; __syncthreads();
    float sum = 0.f;
    #pragma unroll
    for (int i = 0; i < 4; i++) { v[i] = __expf(v[i] - mx); sum += v[i]; }
    red[t] = sum; __syncthreads();
    for (int o = 128; o > 0; o >>= 1) {
        if (t < o) red[t] += red[t+o];
        __syncthreads();
    }
    float inv = 1.f / red[0];
    #pragma unroll
    for (int i = 0; i < 4; i++) p[t + i*256] = rtf(v[i] * inv);
}

// ---------------- CA softmax: 131072 rows x 77 (ld 96), zero-pad 77..95 ----------------
__global__ void softmax77(float* __restrict__ S)
{
    int warp = (blockIdx.x * 256 + threadIdx.x) >> 5;
    int l = threadIdx.x & 31;
    float* p = S + (long long)warp * 96;
    float v0 = p[l];
    float v1 = p[l + 32];
    float v2 = (l + 64 < 77) ? p[l + 64] : -1e30f;
    float mx = fmaxf(v0, fmaxf(v1, v2));
    #pragma unroll
    for (int off = 16; off > 0; off >>= 1)
        mx = fmaxf(mx, __shfl_xor_sync(0xFFFFFFFFu, mx, off));
    float e0 = __expf(v0 - mx), e1 = __expf(v1 - mx);
    float e2 = (l + 64 < 77) ? __expf(v2 - mx) : 0.f;
    float sum = e0 + e1 + e2;
    #pragma unroll
    for (int off = 16; off > 0; off >>= 1)
        sum += __shfl_xor_sync(0xFFFFFFFFu, sum, off);
    float inv = 1.f / sum;
    p[l]      = rtf(e0 * inv);
    p[l + 32] = rtf(e1 * inv);
    p[l + 64] = (l + 64 < 77) ? rtf(e2 * inv) : 0.f;
}

// =======================================================================
// tf32 mma.sync NT GEMM: C[M,N] = alpha * A[M,K] @ W[N,K]^T (+ epilogues)
// 128x128 CTA tile, 4 warps x (64x64) warp tiles, 128 threads,
// 3-stage cp.async pipeline, one __syncthreads per chunk, 2 CTAs/SM.
// =======================================================================
#define EP_STORE   0
#define EP_RES2    1
#define EP_RES1    2
#define EP_TRANSX  3
#define EP_STORET  4
#define EP_STORECV 5

#define BK    32
#define PADW  36
#define TSZ   (128*PADW)
#define BUFSZ (2*TSZ)
#define NSTAGE 3
#define SMEM_MMA (NSTAGE*BUFSZ*4)   // 110592 bytes

template<int CVTA>
__global__ __launch_bounds__(128, 2)
void gemm_mma(const float* __restrict__ A, const float* __restrict__ W,
              float* __restrict__ C, const float* __restrict__ bias,
              const float* __restrict__ xin, float* __restrict__ outx,
              int M, int K, int lda, int ldw, int ldc,
              int wrowmax, int nvalid, float alpha, int mode, int roundC,
              int HZ, long long sAb, long long sAh,
              long long sWb, long long sWh, long long sCb, long long sCh)
{
    extern __shared__ float smem[];
    {
        int z = blockIdx.z;
        int zb = z, zh = 0;
        if (HZ > 1) { zb = z / HZ; zh = z - zb * HZ; }
        A += zb*sAb + zh*sAh;
        W += zb*sWb + zh*sWh;
        C += zb*sCb + zh*sCh;
    }

    const int m0 = blockIdx.y * 128, n0 = blockIdx.x * 128;
    const int tid = threadIdx.x;
    const int wid = tid >> 5, lane = tid & 31;
    const int wm = wid & 1, wn = wid >> 1;      // 2x2 warp grid, 64x64 per warp
    const int rowmax = M - m0;
    const uint32_t sbase = smem_u32(smem);

    const float* Ag = A + (long long)m0 * lda;

    float acc[4][8][4];
    #pragma unroll
    for (int i = 0; i < 4; i++)
        #pragma unroll
        for (int j = 0; j < 8; j++)
            #pragma unroll
            for (int r = 0; r < 4; r++) acc[i][j][r] = 0.f;

    const int nch = K >> 5;

    auto load_tiles = [&](int buf, int c) {
        uint32_t sA4 = sbase + buf * (BUFSZ * 4);
        uint32_t sW4 = sA4 + TSZ * 4;
        const float* Agk = Ag + c * BK;
        #pragma unroll
        for (int i = 0; i < 8; i++) {
            int f = tid + 128 * i;            // 0..1023
            int r = f >> 3, c4 = f & 7;
            int ra = (r < rowmax) ? r : (rowmax - 1);
            cp16(sA4 + (r * PADW + c4 * 4) * 4, Agk + (long long)ra * lda + c4 * 4);
        }
        #pragma unroll
        for (int i = 0; i < 8; i++) {
            int f = tid + 128 * i;
            int r = f >> 3, c4 = f & 7;
            int rw = (n0 + r < wrowmax) ? (n0 + r) : (wrowmax - 1);
            cp16(sW4 + (r * PADW + c4 * 4) * 4, W + (long long)rw * ldw + c * BK + c4 * 4);
        }
        asm volatile("cp.async.commit_group;" ::: "memory");
    };

    // prologue: prefetch chunks 0 and 1 (nch >= 2 for all call sites)
    load_tiles(0, 0);
    load_tiles(1, 1);

    const int frow = lane >> 2;
    const int fcol = lane & 3;

    int buf = 0;
    int lb  = 2;
    for (int c = 0; c < nch; c++) {
        asm volatile("cp.async.wait_group 1;" ::: "memory");
        __syncthreads();
        if (c + 2 < nch) {
            load_tiles(lb, c + 2);
        } else {
            asm volatile("cp.async.commit_group;" ::: "memory");
        }

        const uint32_t* As = (const uint32_t*)smem + buf * BUFSZ;
        const uint32_t* Ws = As + TSZ;
        const uint32_t* Aw = As + wm * 64 * PADW;
        const uint32_t* Ww = Ws + wn * 64 * PADW;

        #pragma unroll
        for (int kk = 0; kk < 4; kk++) {
            const int kb = kk * 8;
            uint32_t a[4][4], b[8][2];
            #pragma unroll
            for (int mf = 0; mf < 4; mf++) {
                const uint32_t* base = Aw + (mf * 16) * PADW + kb;
                a[mf][0] = base[frow * PADW + fcol];
                a[mf][1] = base[(frow + 8) * PADW + fcol];
                a[mf][2] = base[frow * PADW + fcol + 4];
                a[mf][3] = base[(frow + 8) * PADW + fcol + 4];
                if (CVTA) {
                    a[mf][0] = f2tf32(__uint_as_float(a[mf][0]));
                    a[mf][1] = f2tf32(__uint_as_float(a[mf][1]));
                    a[mf][2] = f2tf32(__uint_as_float(a[mf][2]));
                    a[mf][3] = f2tf32(__uint_as_float(a[mf][3]));
                }
            }
            #pragma unroll
            for (int nf = 0; nf < 8; nf++) {
                const uint32_t* base = Ww + (nf * 8 + frow) * PADW + kb;
                b[nf][0] = base[fcol];
                b[nf][1] = base[fcol + 4];
            }
            #pragma unroll
            for (int mf = 0; mf < 4; mf++)
                #pragma unroll
                for (int nf = 0; nf < 8; nf++)
                    mma_tf32(acc[mf][nf], a[mf], b[nf]);
        }
        buf = (buf == NSTAGE-1) ? 0 : buf + 1;
        lb  = (lb  == NSTAGE-1) ? 0 : lb  + 1;
    }

    // ---- epilogue ----
    #pragma unroll
    for (int mf = 0; mf < 4; mf++) {
        #pragma unroll
        for (int nf = 0; nf < 8; nf++) {
            int rg  = m0 + wm * 64 + mf * 16 + frow;
            int cg  = n0 + wn * 64 + nf * 8 + 2 * fcol;
            bool g0 = cg < nvalid, g1 = cg + 1 < nvalid;
            #pragma unroll
            for (int half = 0; half < 2; half++) {
                int row = rg + half * 8;
                if (row >= M) continue;
                float v0 = alpha * acc[mf][nf][half * 2 + 0];
                float v1 = alpha * acc[mf][nf][half * 2 + 1];
                if (bias) {
                    if (g0) v0 += bias[cg];
                    if (g1) v1 += bias[cg + 1];
                }
                if (roundC) { v0 = rtf(v0); v1 = rtf(v1); }
                if (mode == EP_TRANSX) {
                    int bb = row >> 10, n = row & 1023;
                    long long o0 = (((long long)bb * CIN + cg) << 10) + n;
                    if (g0) outx[o0]        = v0 + xin[o0];
                    if (g1) outx[o0 + 1024] = v1 + xin[o0 + 1024];
                } else if (mode == EP_STORET) {
                    int bb = row >> 10, n = row & 1023;
                    long long o0 = (((long long)bb * INNER + cg) << 10) + n;
                    C[o0]        = v0;
                    C[o0 + 1024] = v1;
                } else if (mode == EP_STORECV) {
                    int bb = row / 77, j = row - bb * 77;
                    int h0 = cg >> 6, d0 = cg & 63;
                    int h1 = (cg + 1) >> 6, d1 = (cg + 1) & 63;
                    C[((long long)(bb * 8 + h0) * 64 + d0) * 96 + j] = v0;
                    C[((long long)(bb * 8 + h1) * 64 + d1) * 96 + j] = v1;
                } else {
                    float* cp = C + (long long)row * ldc + cg;
                    if (mode == EP_RES2)      { if (g0) v0 += 2.f * cp[0]; if (g1) v1 += 2.f * cp[1]; }
                    else if (mode == EP_RES1) { if (g0) v0 += cp[0];       if (g1) v1 += cp[1]; }
                    if (g0) cp[0] = v0;
                    if (g1) cp[1] = v1;
                }
            }
        }
    }
}

// =======================================================================
// host launch
// =======================================================================
extern "C" void kernel_launch(void* const* d_in, const int* in_sizes, int n_in,
                              void* d_out, int out_size)
{
    const float* x      = (const float*)d_in[0];
    const float* ctx    = (const float*)d_in[1];
    const float* gn1_g  = (const float*)d_in[2];
    const float* gn1_b  = (const float*)d_in[3];
    const float* w_in   = (const float*)d_in[4];
    const float* b_in   = (const float*)d_in[5];
    const float* sa_wk  = (const float*)d_in[6];
    const float* sa_wq  = (const float*)d_in[7];
    const float* sa_wv  = (const float*)d_in[8];
    const float* sa_wp  = (const float*)d_in[9];
    const float* sa_gng = (const float*)d_in[10];
    const float* sa_gnb = (const float*)d_in[11];
    const float* ca_wq  = (const float*)d_in[12];
    const float* ca_wk  = (const float*)d_in[13];
    const float* ca_wv  = (const float*)d_in[14];
    const float* ca_wo  = (const float*)d_in[15];
    const float* ca_bo  = (const float*)d_in[16];
    const float* w_out  = (const float*)d_in[17];
    const float* b_out  = (const float*)d_in[18];
    float* out = (float*)d_out;

    float *p_gn1, *p_h, *p_hn, *p_q, *p_k, *p_v, *p_sim, *p_o, *p_k2, *p_wr;
    cudaGetSymbolAddress((void**)&p_gn1, g_gn1);
    cudaGetSymbolAddress((void**)&p_h,   g_h);
    cudaGetSymbolAddress((void**)&p_hn,  g_hn);
    cudaGetSymbolAddress((void**)&p_q,   g_q);
    cudaGetSymbolAddress((void**)&p_k,   g_k);
    cudaGetSymbolAddress((void**)&p_v,   g_v);
    cudaGetSymbolAddress((void**)&p_sim, g_sim);
    cudaGetSymbolAddress((void**)&p_o,   g_o);
    cudaGetSymbolAddress((void**)&p_k2,  g_k2);
    cudaGetSymbolAddress((void**)&p_wr,  g_wr);

    cudaFuncSetAttribute(gemm_mma<0>, cudaFuncAttributeMaxDynamicSharedMemorySize, SMEM_MMA);
    cudaFuncSetAttribute(gemm_mma<1>, cudaFuncAttributeMaxDynamicSharedMemorySize, SMEM_MMA);
    cudaFuncSetAttribute(gn1_kernel,  cudaFuncAttributeMaxDynamicSharedMemorySize, 32768);
    cudaFuncSetAttribute(gn2_kernel,  cudaFuncAttributeMaxDynamicSharedMemorySize, 65536);

    const float simScale = 0.044194173824159216f; // 512^-0.5

    // 0. pre-round weights
    wround_kernel<<<WTOT/1024, 1024>>>(w_in, sa_wq, sa_wk, sa_wv, sa_wp,
                                       ca_wq, ca_wk, ca_wv, ca_wo, w_out, p_wr);

    // 1. GroupNorm1 -> token-major (rounded)
    gn1_kernel<<<BATCH*32, 256, 32768>>>(x, gn1_g, gn1_b, p_gn1);

    // 2. conv_in: h = gn1 @ w_in^T + b_in (full precision store)
    gemm_mma<0><<<dim3(4,128,1), 128, SMEM_MMA>>>(p_gn1, p_wr+OFF_WIN, p_h, b_in, nullptr, nullptr,
        MTOK, CIN, CIN, CIN, INNER, INNER, INNER, 1.f, EP_STORE, 0, 1, 0,0, 0,0, 0,0);

    // 3. SA groupnorm (rounded)
    gn2_kernel<<<BATCH*32, 256, 65536>>>(p_h, sa_gng, sa_gnb, p_hn);

    // 4. q/k/v projections (rounded; v stored transposed per batch)
    gemm_mma<0><<<dim3(4,128,1), 128, SMEM_MMA>>>(p_hn, p_wr+OFF_SAQ, p_q, nullptr, nullptr, nullptr,
        MTOK, INNER, INNER, INNER, INNER, INNER, INNER, 1.f, EP_STORE, 1, 1, 0,0, 0,0, 0,0);
    gemm_mma<0><<<dim3(4,128,1), 128, SMEM_MMA>>>(p_hn, p_wr+OFF_SAK, p_k, nullptr, nullptr, nullptr,
        MTOK, INNER, INNER, INNER, INNER, INNER, INNER, 1.f, EP_STORE, 1, 1, 0,0, 0,0, 0,0);
    gemm_mma<0><<<dim3(4,128,1), 128, SMEM_MMA>>>(p_hn, p_wr+OFF_SAV, p_v, nullptr, nullptr, nullptr,
        MTOK, INNER, INNER, INNER, INNER, INNER, INNER, 1.f, EP_STORET, 1, 1, 0,0, 0,0, 0,0);

    // 5. sim = scale * q @ k^T (batched; full precision, softmax rounds)
    gemm_mma<0><<<dim3(8,8,BATCH), 128, SMEM_MMA>>>(p_q, p_k, p_sim, nullptr, nullptr, nullptr,
        NTOK, INNER, INNER, INNER, NTOK, NTOK, NTOK, simScale, EP_STORE, 0, 1,
        (long long)NTOK*INNER, 0, (long long)NTOK*INNER, 0, (long long)NTOK*NTOK, 0);

    // 6. SA softmax (rounded)
    softmax_rows<<<MTOK, 256>>>(p_sim);

    // 7. o = P @ vT^T (batched NT; rounded)
    gemm_mma<0><<<dim3(4,8,BATCH), 128, SMEM_MMA>>>(p_sim, p_v, p_o, nullptr, nullptr, nullptr,
        NTOK, NTOK, NTOK, NTOK, INNER, INNER, INNER, 1.f, EP_STORE, 1, 1,
        (long long)NTOK*NTOK, 0, (long long)INNER*NTOK, 0, (long long)NTOK*INNER, 0);

    // 8. h = 2*h + o @ sa_wp^T (full precision)
    gemm_mma<0><<<dim3(4,128,1), 128, SMEM_MMA>>>(p_o, p_wr+OFF_SAP, p_h, nullptr, nullptr, nullptr,
        MTOK, INNER, INNER, INNER, INNER, INNER, INNER, 1.f, EP_RES2, 0, 1, 0,0, 0,0, 0,0);

    // 9. CA q = h @ ca_wq^T (A unrounded -> CVTA; rounded store)
    gemm_mma<1><<<dim3(4,128,1), 128, SMEM_MMA>>>(p_h, p_wr+OFF_CAQ, p_q, nullptr, nullptr, nullptr,
        MTOK, INNER, INNER, INNER, INNER, INNER, INNER, 1.f, EP_STORE, 1, 1, 0,0, 0,0, 0,0);

    // 10/11. CA k (rounded), v (per-head transposed into g_v, rounded)
    gemm_mma<1><<<dim3(4,10,1), 128, SMEM_MMA>>>(ctx, p_wr+OFF_CAK, p_k2, nullptr, nullptr, nullptr,
        MCTX, CTXD, CTXD, CTXD, INNER, INNER, INNER, 1.f, EP_STORE, 1, 1, 0,0, 0,0, 0,0);
    gemm_mma<1><<<dim3(4,10,1), 128, SMEM_MMA>>>(ctx, p_wr+OFF_CAV, p_v, nullptr, nullptr, nullptr,
        MCTX, CTXD, CTXD, CTXD, INNER, INNER, INNER, 1.f, EP_STORECV, 1, 1, 0,0, 0,0, 0,0);

    // 12. CA sim2 = 0.125 * Q_head @ K2_head^T  [128 batches of (1024 x 77 x 64)]
    gemm_mma<0><<<dim3(1,8,128), 128, SMEM_MMA>>>(p_q, p_k2, p_sim, nullptr, nullptr, nullptr,
        NTOK, 64, INNER, INNER, 96, CTXN, CTXN, 0.125f, EP_STORE, 0, 8,
        (long long)NTOK*INNER, 64, (long long)CTXN*INNER, 64,
        (long long)8*NTOK*96, (long long)NTOK*96);

    // 13. CA softmax over 77 (rounded, zero-pads to 96)
    softmax77<<<16384, 256>>>(p_sim);

    // 14. CA o = P @ v2t^T  [128 batches of (1024 x 64 x 96)] (rounded)
    gemm_mma<0><<<dim3(1,8,128), 128, SMEM_MMA>>>(p_sim, p_v, p_o, nullptr, nullptr, nullptr,
        NTOK, 96, 96, 96, INNER, 64, 64, 1.f, EP_STORE, 1, 8,
        (long long)8*NTOK*96, (long long)NTOK*96, (long long)8*64*96, (long long)64*96,
        (long long)NTOK*INNER, 64);

    // 15. h = h + (o @ ca_wo^T + ca_bo) (full precision)
    gemm_mma<0><<<dim3(4,128,1), 128, SMEM_MMA>>>(p_o, p_wr+OFF_CAO, p_h, ca_bo, nullptr, nullptr,
        MTOK, INNER, INNER, INNER, INNER, INNER, INNER, 1.f, EP_RES1, 0, 1, 0,0, 0,0, 0,0);

    // 16. out = transpose(h @ w_out^T + b_out) + x (A unrounded -> CVTA)
    gemm_mma<1><<<dim3(2,128,1), 128, SMEM_MMA>>>(p_h, p_wr+OFF_WOUT, nullptr, b_out, x, out,
        MTOK, INNER, INNER, INNER, CIN, CIN, CIN, 1.f, EP_TRANSX, 0, 1, 0,0, 0,0, 0,0);
}

// round 13
// speedup vs baseline: 1.4332x; 1.4332x over previous
#include <cuda_runtime.h>
#include <cstdint>
#include <math.h>

// ---------------- problem constants ----------------
#define BATCH   16
#define NTOK    1024
#define CIN     256
#define INNER   512
#define CTXN    77
#define CTXD    768
#define MTOK    (BATCH*NTOK)  // 16384
#define MCTX    (BATCH*CTXN)  // 1232

// rounded-weight scratch offsets
#define OFF_WIN  0
#define OFF_SAQ  131072
#define OFF_SAK  393216
#define OFF_SAV  655360
#define OFF_SAP  917504
#define OFF_CAQ  1179648
#define OFF_CAK  1441792
#define OFF_CAV  1835008
#define OFF_CAO  2228224
#define OFF_WOUT 2490368
#define WTOT     2621440

// ---------------- scratch (device globals; no allocation) ----------------
__device__ float g_gn1[MTOK*CIN];
__device__ float g_h  [MTOK*INNER];
__device__ float g_hn [MTOK*INNER];
__device__ float g_q  [MTOK*INNER];
__device__ float g_k  [MTOK*INNER];
__device__ float g_v  [MTOK*INNER];      // SA: vT [B][512][1024]; later CA: v2t [128][64][96]
__device__ float g_sim[16777216];        // SA: B*N*N; CA: [128][1024][96]
__device__ float g_o  [MTOK*INNER];
__device__ float g_k2 [MCTX*INNER];
__device__ float g_wr [WTOT];            // pre-rounded weights

// ---------------- tf32 helpers ----------------
__device__ __forceinline__ uint32_t f2tf32(float f) {
    uint32_t r;
    asm("cvt.rna.tf32.f32 %0, %1;" : "=r"(r) : "f"(f));
    return r;
}
__device__ __forceinline__ float rtf(float f) { return __uint_as_float(f2tf32(f)); }

__device__ __forceinline__ void cp16(uint32_t dst, const float* src) {
    asm volatile("cp.async.cg.shared.global [%0], [%1], 16;" :: "r"(dst), "l"(src));
}
__device__ __forceinline__ uint32_t smem_u32(const void* p) {
    uint32_t a;
    asm("{ .reg .u64 t; cvta.to.shared.u64 t, %1; cvt.u32.u64 %0, t; }" : "=r"(a) : "l"(p));
    return a;
}
__device__ __forceinline__ void mma_tf32(float* c, const uint32_t* a, const uint32_t* b) {
    asm volatile("mma.sync.aligned.m16n8k8.row.col.f32.tf32.tf32.f32 "
                 "{%0,%1,%2,%3}, {%4,%5,%6,%7}, {%8,%9}, {%0,%1,%2,%3};"
                 : "+f"(c[0]), "+f"(c[1]), "+f"(c[2]), "+f"(c[3])
                 : "r"(a[0]), "r"(a[1]), "r"(a[2]), "r"(a[3]), "r"(b[0]), "r"(b[1]));
}
// ldmatrix: 4x (8 rows x 16B) -> exactly the m16k8 tf32 A-fragment quad
__device__ __forceinline__ void ldsm_x4(uint32_t* r, uint32_t addr) {
    asm volatile("ldmatrix.sync.aligned.x4.m8n8.shared.b16 {%0,%1,%2,%3}, [%4];"
                 : "=r"(r[0]), "=r"(r[1]), "=r"(r[2]), "=r"(r[3]) : "r"(addr));
}
// ldmatrix: 2x (8 rows x 16B) -> the n8k8 tf32 B-fragment pair
__device__ __forceinline__ void ldsm_x2(uint32_t* r, uint32_t addr) {
    asm volatile("ldmatrix.sync.aligned.x2.m8n8.shared.b16 {%0,%1}, [%2];"
                 : "=r"(r[0]), "=r"(r[1]) : "r"(addr));
}

// ---------------- weight pre-rounding ----------------
__global__ void wround_kernel(const float* __restrict__ w0, const float* __restrict__ w1,
                              const float* __restrict__ w2, const float* __restrict__ w3,
                              const float* __restrict__ w4, const float* __restrict__ w5,
                              const float* __restrict__ w6, const float* __restrict__ w7,
                              const float* __restrict__ w8, const float* __restrict__ w9,
                              float* __restrict__ dst)
{
    int i = blockIdx.x * 1024 + threadIdx.x;
    const float* s; int off;
    if      (i < OFF_SAQ)  { s = w0; off = OFF_WIN;  }
    else if (i < OFF_SAK)  { s = w1; off = OFF_SAQ;  }
    else if (i < OFF_SAV)  { s = w2; off = OFF_SAK;  }
    else if (i < OFF_SAP)  { s = w3; off = OFF_SAV;  }
    else if (i < OFF_CAQ)  { s = w4; off = OFF_SAP;  }
    else if (i < OFF_CAK)  { s = w5; off = OFF_CAQ;  }
    else if (i < OFF_CAV)  { s = w6; off = OFF_CAK;  }
    else if (i < OFF_CAO)  { s = w7; off = OFF_CAV;  }
    else if (i < OFF_WOUT) { s = w8; off = OFF_CAO;  }
    else                   { s = w9; off = OFF_WOUT; }
    dst[i] = rtf(s[i - off]);
}

// ---------------- GroupNorm 1 (single pass via smem cache; rounded store) ----------------
__global__ void gn1_kernel(const float* __restrict__ x, const float* __restrict__ gam,
                           const float* __restrict__ bet, float* __restrict__ out)
{
    extern __shared__ float cache[];
    int bg = blockIdx.x;
    int b  = bg >> 5, grp = bg & 31;
    const float* xb = x + ((long)b*CIN + grp*8) * NTOK;
    __shared__ float r1[256], r2[256];
    int t = threadIdx.x;
    float s = 0.f, s2 = 0.f;
    for (int i = t; i < 8192; i += 256) {
        float v = xb[i]; cache[i] = v; s += v; s2 += v*v;
    }
    r1[t] = s; r2[t] = s2; __syncthreads();
    for (int o = 128; o > 0; o >>= 1) {
        if (t < o) { r1[t] += r1[t+o]; r2[t] += r2[t+o]; }
        __syncthreads();
    }
    float mean = r1[0] * (1.f/8192.f);
    float var  = r2[0] * (1.f/8192.f) - mean*mean;
    float rstd = rsqrtf(var + 1e-5f);
    for (int i = t; i < 8192; i += 256) {
        int c = grp*8 + (i >> 10);
        int n = i & 1023;
        float v = (cache[i] - mean) * rstd * gam[c] + bet[c];
        out[((long)b*NTOK + n)*CIN + c] = rtf(v);
    }
}

// ---------------- GroupNorm 2 (single pass via smem cache; rounded store) ----------------
__global__ void gn2_kernel(const float* __restrict__ h, const float* __restrict__ gam,
                           const float* __restrict__ bet, float* __restrict__ out)
{
    extern __shared__ float cache[];
    int bg = blockIdx.x;
    int b  = bg >> 5, grp = bg & 31;
    const float* hb = h + (long)b*NTOK*INNER;
    float* ob = out + (long)b*NTOK*INNER;
    __shared__ float r1[256], r2[256];
    int t = threadIdx.x;
    float s = 0.f, s2 = 0.f;
    for (int i = t; i < 16384; i += 256) {
        int n = i >> 4, c = grp*16 + (i & 15);
        float v = hb[n*INNER + c];
        cache[i] = v; s += v; s2 += v*v;
    }
    r1[t] = s; r2[t] = s2; __syncthreads();
    for (int o = 128; o > 0; o >>= 1) {
        if (t < o) { r1[t] += r1[t+o]; r2[t] += r2[t+o]; }
        __syncthreads();
    }
    float mean = r1[0] * (1.f/16384.f);
    float var  = r2[0] * (1.f/16384.f) - mean*mean;
    float rstd = rsqrtf(var + 1e-5f);
    for (int i = t; i < 16384; i += 256) {
        int n = i >> 4, c = grp*16 + (i & 15);
        ob[n*INNER + c] = rtf((cache[i] - mean) * rstd * gam[c] + bet[c]);
    }
}

// ---------------- SA row softmax: 16384 rows x 1024 (rounded store) ----------------
__global__ void softmax_rows(float* __restrict__ S)
{
    long long row = blockIdx.x;
    float* p = S + row * 1024;
    __shared__ float red[256];
    int t = threadIdx.x;
    float v[4];
    float mx = -1e30f;
    #pragma unroll
    for (int i = 0; i < 4; i++) { v[i] = p[t + i*256]; mx = fmaxf(mx, v[i]); }
    red[t] = mx; __syncthreads();
    for (int o = 128; o > 0; o >>= 1) {
        if (t < o) red[t] = fmaxf(red[t], red[t+o]);
        __syncthreads();
    }
    mx = red[0]; __syncthreads();
    float sum = 0.f;
    #pragma unroll
    for (int i = 0; i < 4; i++) { v[i] = __expf(v[i] - mx); sum += v[i]; }
    red[t] = sum; __syncthreads();
    for (int o = 128; o > 0; o >>= 1) {
        if (t < o) red[t] += red[t+o];
        __syncthreads();
    }
    float inv = 1.f / red[0];
    #pragma unroll
    for (int i = 0; i < 4; i++) p[t + i*256] = rtf(v[i] * inv);
}

// ---------------- CA softmax: 131072 rows x 77 (ld 96), zero-pad 77..95 ----------------
__global__ void softmax77(float* __restrict__ S)
{
    int warp = (blockIdx.x * 256 + threadIdx.x) >> 5;
    int l = threadIdx.x & 31;
    float* p = S + (long long)warp * 96;
    float v0 = p[l];
    float v1 = p[l + 32];
    float v2 = (l + 64 < 77) ? p[l + 64] : -1e30f;
    float mx = fmaxf(v0, fmaxf(v1, v2));
    #pragma unroll
    for (int off = 16; off > 0; off >>= 1)
        mx = fmaxf(mx, __shfl_xor_sync(0xFFFFFFFFu, mx, off));
    float e0 = __expf(v0 - mx), e1 = __expf(v1 - mx);
    float e2 = (l + 64 < 77) ? __expf(v2 - mx) : 0.f;
    float sum = e0 + e1 + e2;
    #pragma unroll
    for (int off = 16; off > 0; off >>= 1)
        sum += __shfl_xor_sync(0xFFFFFFFFu, sum, off);
    float inv = 1.f / sum;
    p[l]      = rtf(e0 * inv);
    p[l + 32] = rtf(e1 * inv);
    p[l + 64] = (l + 64 < 77) ? rtf(e2 * inv) : 0.f;
}

// =======================================================================
// tf32 mma.sync NT GEMM: C[M,N] = alpha * A[M,K] @ W[N,K]^T (+ epilogues)
// 128x128 CTA, 8 warps x (64x32), 3-stage cp.async, ldmatrix fragment loads.
// =======================================================================
#define EP_STORE   0
#define EP_RES2    1
#define EP_RES1    2
#define EP_TRANSX  3
#define EP_STORET  4
#define EP_STORECV 5

#define BK    32
#define PADW  36
#define TSZ   (128*PADW)
#define BUFSZ (2*TSZ)
#define NSTAGE 3
#define SMEM_MMA (NSTAGE*BUFSZ*4)   // 110592 bytes

template<int CVTA>
__global__ __launch_bounds__(256, 2)
void gemm_mma(const float* __restrict__ A, const float* __restrict__ W,
              float* __restrict__ C, const float* __restrict__ bias,
              const float* __restrict__ xin, float* __restrict__ outx,
              int M, int K, int lda, int ldw, int ldc,
              int wrowmax, int nvalid, float alpha, int mode, int roundC,
              int HZ, long long sAb, long long sAh,
              long long sWb, long long sWh, long long sCb, long long sCh)
{
    extern __shared__ float smem[];
    {
        int z = blockIdx.z;
        int zb = z, zh = 0;
        if (HZ > 1) { zb = z / HZ; zh = z - zb * HZ; }
        A += zb*sAb + zh*sAh;
        W += zb*sWb + zh*sWh;
        C += zb*sCb + zh*sCh;
    }

    const int m0 = blockIdx.y * 128, n0 = blockIdx.x * 128;
    const int tid = threadIdx.x;
    const int wid = tid >> 5, lane = tid & 31;
    const int wm = wid & 1, wn = wid >> 1;      // 2x4 warp grid, 64x32 tiles
    const int rowmax = M - m0;
    const uint32_t sbase = smem_u32(smem);

    const float* Ag = A + (long long)m0 * lda;

    float acc[4][4][4];
    #pragma unroll
    for (int i = 0; i < 4; i++)
        #pragma unroll
        for (int j = 0; j < 4; j++)
            #pragma unroll
            for (int r = 0; r < 4; r++) acc[i][j][r] = 0.f;

    const int nch = K >> 5;

    auto load_tiles = [&](int buf, int c) {
        uint32_t sA4 = sbase + buf * (BUFSZ * 4);
        uint32_t sW4 = sA4 + TSZ * 4;
        const float* Agk = Ag + c * BK;
        #pragma unroll
        for (int i = 0; i < 4; i++) {
            int f = tid + 256 * i;
            int r = f >> 3, c4 = f & 7;
            int ra = (r < rowmax) ? r : (rowmax - 1);
            cp16(sA4 + (r * PADW + c4 * 4) * 4, Agk + (long long)ra * lda + c4 * 4);
        }
        #pragma unroll
        for (int i = 0; i < 4; i++) {
            int f = tid + 256 * i;
            int r = f >> 3, c4 = f & 7;
            int rw = (n0 + r < wrowmax) ? (n0 + r) : (wrowmax - 1);
            cp16(sW4 + (r * PADW + c4 * 4) * 4, W + (long long)rw * ldw + c * BK + c4 * 4);
        }
        asm volatile("cp.async.commit_group;" ::: "memory");
    };

    load_tiles(0, 0);
    load_tiles(1, 1);

    const int frow = lane >> 2;
    const int fcol = lane & 3;

    // per-lane ldmatrix row offsets (bytes)
    // A quad (x4): mats = {m0-7,k0-3},{m8-15,k0-3},{m0-7,k4-7},{m8-15,k4-7}
    const uint32_t aoff = ((uint32_t)(wm * 64 + ((lane >> 3) & 1) * 8 + (lane & 7)) * PADW
                          + (uint32_t)(lane >> 4) * 4) * 4;
    // B pair (x2): mats = {n0-7,k0-3},{n0-7,k4-7}; lanes 0-15 supply addresses
    const uint32_t boff = ((uint32_t)(wn * 32 + (lane & 7)) * PADW
                          + (uint32_t)((lane >> 3) & 1) * 4) * 4;

    int buf = 0, lb = 2;
    for (int c = 0; c < nch; c++) {
        asm volatile("cp.async.wait_group 1;" ::: "memory");
        __syncthreads();
        if (c + 2 < nch) {
            load_tiles(lb, c + 2);
        } else {
            asm volatile("cp.async.commit_group;" ::: "memory");
        }

        const uint32_t sA = sbase + buf * (BUFSZ * 4);
        const uint32_t sW = sA + TSZ * 4;

        #pragma unroll
        for (int kk = 0; kk < 4; kk++) {
            const uint32_t kbB = kk * 8 * 4;   // k-offset bytes
            uint32_t a[4][4], b[4][2];
            #pragma unroll
            for (int mf = 0; mf < 4; mf++) {
                ldsm_x4(a[mf], sA + aoff + (uint32_t)(mf * 16 * PADW) * 4 + kbB);
                if (CVTA) {
                    a[mf][0] = f2tf32(__uint_as_float(a[mf][0]));
                    a[mf][1] = f2tf32(__uint_as_float(a[mf][1]));
                    a[mf][2] = f2tf32(__uint_as_float(a[mf][2]));
                    a[mf][3] = f2tf32(__uint_as_float(a[mf][3]));
                }
            }
            #pragma unroll
            for (int nf = 0; nf < 4; nf++)
                ldsm_x2(b[nf], sW + boff + (uint32_t)(nf * 8 * PADW) * 4 + kbB);
            #pragma unroll
            for (int mf = 0; mf < 4; mf++)
                #pragma unroll
                for (int nf = 0; nf < 4; nf++)
                    mma_tf32(acc[mf][nf], a[mf], b[nf]);
        }
        buf = (buf == NSTAGE-1) ? 0 : buf + 1;
        lb  = (lb  == NSTAGE-1) ? 0 : lb  + 1;
    }

    // ---- epilogue ----
    #pragma unroll
    for (int mf = 0; mf < 4; mf++) {
        #pragma unroll
        for (int nf = 0; nf < 4; nf++) {
            int rg  = m0 + wm * 64 + mf * 16 + frow;
            int cg  = n0 + wn * 32 + nf * 8 + 2 * fcol;
            bool g0 = cg < nvalid, g1 = cg + 1 < nvalid;
            #pragma unroll
            for (int half = 0; half < 2; half++) {
                int row = rg + half * 8;
                if (row >= M) continue;
                float v0 = alpha * acc[mf][nf][half * 2 + 0];
                float v1 = alpha * acc[mf][nf][half * 2 + 1];
                if (bias) {
                    if (g0) v0 += bias[cg];
                    if (g1) v1 += bias[cg + 1];
                }
                if (roundC) { v0 = rtf(v0); v1 = rtf(v1); }
                if (mode == EP_TRANSX) {
                    int bb = row >> 10, n = row & 1023;
                    long long o0 = (((long long)bb * CIN + cg) << 10) + n;
                    if (g0) outx[o0]        = v0 + xin[o0];
                    if (g1) outx[o0 + 1024] = v1 + xin[o0 + 1024];
                } else if (mode == EP_STORET) {
                    int bb = row >> 10, n = row & 1023;
                    long long o0 = (((long long)bb * INNER + cg) << 10) + n;
                    C[o0]        = v0;
                    C[o0 + 1024] = v1;
                } else if (mode == EP_STORECV) {
                    int bb = row / 77, j = row - bb * 77;
                    int h0 = cg >> 6, d0 = cg & 63;
                    int h1 = (cg + 1) >> 6, d1 = (cg + 1) & 63;
                    C[((long long)(bb * 8 + h0) * 64 + d0) * 96 + j] = v0;
                    C[((long long)(bb * 8 + h1) * 64 + d1) * 96 + j] = v1;
                } else {
                    float* cp = C + (long long)row * ldc + cg;
                    if (mode == EP_RES2)      { if (g0) v0 += 2.f * cp[0]; if (g1) v1 += 2.f * cp[1]; }
                    else if (mode == EP_RES1) { if (g0) v0 += cp[0];       if (g1) v1 += cp[1]; }
                    if (g0) cp[0] = v0;
                    if (g1) cp[1] = v1;
                }
            }
        }
    }
}

// =======================================================================
// host launch
// =======================================================================
extern "C" void kernel_launch(void* const* d_in, const int* in_sizes, int n_in,
                              void* d_out, int out_size)
{
    const float* x      = (const float*)d_in[0];
    const float* ctx    = (const float*)d_in[1];
    const float* gn1_g  = (const float*)d_in[2];
    const float* gn1_b  = (const float*)d_in[3];
    const float* w_in   = (const float*)d_in[4];
    const float* b_in   = (const float*)d_in[5];
    const float* sa_wk  = (const float*)d_in[6];
    const float* sa_wq  = (const float*)d_in[7];
    const float* sa_wv  = (const float*)d_in[8];
    const float* sa_wp  = (const float*)d_in[9];
    const float* sa_gng = (const float*)d_in[10];
    const float* sa_gnb = (const float*)d_in[11];
    const float* ca_wq  = (const float*)d_in[12];
    const float* ca_wk  = (const float*)d_in[13];
    const float* ca_wv  = (const float*)d_in[14];
    const float* ca_wo  = (const float*)d_in[15];
    const float* ca_bo  = (const float*)d_in[16];
    const float* w_out  = (const float*)d_in[17];
    const float* b_out  = (const float*)d_in[18];
    float* out = (float*)d_out;

    float *p_gn1, *p_h, *p_hn, *p_q, *p_k, *p_v, *p_sim, *p_o, *p_k2, *p_wr;
    cudaGetSymbolAddress((void**)&p_gn1, g_gn1);
    cudaGetSymbolAddress((void**)&p_h,   g_h);
    cudaGetSymbolAddress((void**)&p_hn,  g_hn);
    cudaGetSymbolAddress((void**)&p_q,   g_q);
    cudaGetSymbolAddress((void**)&p_k,   g_k);
    cudaGetSymbolAddress((void**)&p_v,   g_v);
    cudaGetSymbolAddress((void**)&p_sim, g_sim);
    cudaGetSymbolAddress((void**)&p_o,   g_o);
    cudaGetSymbolAddress((void**)&p_k2,  g_k2);
    cudaGetSymbolAddress((void**)&p_wr,  g_wr);

    cudaFuncSetAttribute(gemm_mma<0>, cudaFuncAttributeMaxDynamicSharedMemorySize, SMEM_MMA);
    cudaFuncSetAttribute(gemm_mma<1>, cudaFuncAttributeMaxDynamicSharedMemorySize, SMEM_MMA);
    cudaFuncSetAttribute(gn1_kernel,  cudaFuncAttributeMaxDynamicSharedMemorySize, 32768);
    cudaFuncSetAttribute(gn2_kernel,  cudaFuncAttributeMaxDynamicSharedMemorySize, 65536);

    const float simScale = 0.044194173824159216f; // 512^-0.5

    // 0. pre-round weights
    wround_kernel<<<WTOT/1024, 1024>>>(w_in, sa_wq, sa_wk, sa_wv, sa_wp,
                                       ca_wq, ca_wk, ca_wv, ca_wo, w_out, p_wr);

    // 1. GroupNorm1 -> token-major (rounded)
    gn1_kernel<<<BATCH*32, 256, 32768>>>(x, gn1_g, gn1_b, p_gn1);

    // 2. conv_in: h = gn1 @ w_in^T + b_in (full precision store)
    gemm_mma<0><<<dim3(4,128,1), 256, SMEM_MMA>>>(p_gn1, p_wr+OFF_WIN, p_h, b_in, nullptr, nullptr,
        MTOK, CIN, CIN, CIN, INNER, INNER, INNER, 1.f, EP_STORE, 0, 1, 0,0, 0,0, 0,0);

    // 3. SA groupnorm (rounded)
    gn2_kernel<<<BATCH*32, 256, 65536>>>(p_h, sa_gng, sa_gnb, p_hn);

    // 4. q/k/v projections (rounded; v stored transposed per batch)
    gemm_mma<0><<<dim3(4,128,1), 256, SMEM_MMA>>>(p_hn, p_wr+OFF_SAQ, p_q, nullptr, nullptr, nullptr,
        MTOK, INNER, INNER, INNER, INNER, INNER, INNER, 1.f, EP_STORE, 1, 1, 0,0, 0,0, 0,0);
    gemm_mma<0><<<dim3(4,128,1), 256, SMEM_MMA>>>(p_hn, p_wr+OFF_SAK, p_k, nullptr, nullptr, nullptr,
        MTOK, INNER, INNER, INNER, INNER, INNER, INNER, 1.f, EP_STORE, 1, 1, 0,0, 0,0, 0,0);
    gemm_mma<0><<<dim3(4,128,1), 256, SMEM_MMA>>>(p_hn, p_wr+OFF_SAV, p_v, nullptr, nullptr, nullptr,
        MTOK, INNER, INNER, INNER, INNER, INNER, INNER, 1.f, EP_STORET, 1, 1, 0,0, 0,0, 0,0);

    // 5. sim = scale * q @ k^T (batched; full precision, softmax rounds)
    gemm_mma<0><<<dim3(8,8,BATCH), 256, SMEM_MMA>>>(p_q, p_k, p_sim, nullptr, nullptr, nullptr,
        NTOK, INNER, INNER, INNER, NTOK, NTOK, NTOK, simScale, EP_STORE, 0, 1,
        (long long)NTOK*INNER, 0, (long long)NTOK*INNER, 0, (long long)NTOK*NTOK, 0);

    // 6. SA softmax (rounded)
    softmax_rows<<<MTOK, 256>>>(p_sim);

    // 7. o = P @ vT^T (batched NT; rounded)
    gemm_mma<0><<<dim3(4,8,BATCH), 256, SMEM_MMA>>>(p_sim, p_v, p_o, nullptr, nullptr, nullptr,
        NTOK, NTOK, NTOK, NTOK, INNER, INNER, INNER, 1.f, EP_STORE, 1, 1,
        (long long)NTOK*NTOK, 0, (long long)INNER*NTOK, 0, (long long)NTOK*INNER, 0);

    // 8. h = 2*h + o @ sa_wp^T (full precision)
    gemm_mma<0><<<dim3(4,128,1), 256, SMEM_MMA>>>(p_o, p_wr+OFF_SAP, p_h, nullptr, nullptr, nullptr,
        MTOK, INNER, INNER, INNER, INNER, INNER, INNER, 1.f, EP_RES2, 0, 1, 0,0, 0,0, 0,0);

    // 9. CA q = h @ ca_wq^T (A unrounded -> CVTA; rounded store)
    gemm_mma<1><<<dim3(4,128,1), 256, SMEM_MMA>>>(p_h, p_wr+OFF_CAQ, p_q, nullptr, nullptr, nullptr,
        MTOK, INNER, INNER, INNER, INNER, INNER, INNER, 1.f, EP_STORE, 1, 1, 0,0, 0,0, 0,0);

    // 10/11. CA k (rounded), v (per-head transposed into g_v, rounded)
    gemm_mma<1><<<dim3(4,10,1), 256, SMEM_MMA>>>(ctx, p_wr+OFF_CAK, p_k2, nullptr, nullptr, nullptr,
        MCTX, CTXD, CTXD, CTXD, INNER, INNER, INNER, 1.f, EP_STORE, 1, 1, 0,0, 0,0, 0,0);
    gemm_mma<1><<<dim3(4,10,1), 256, SMEM_MMA>>>(ctx, p_wr+OFF_CAV, p_v, nullptr, nullptr, nullptr,
        MCTX, CTXD, CTXD, CTXD, INNER, INNER, INNER, 1.f, EP_STORECV, 1, 1, 0,0, 0,0, 0,0);

    // 12. CA sim2 = 0.125 * Q_head @ K2_head^T  [128 batches of (1024 x 77 x 64)]
    gemm_mma<0><<<dim3(1,8,128), 256, SMEM_MMA>>>(p_q, p_k2, p_sim, nullptr, nullptr, nullptr,
        NTOK, 64, INNER, INNER, 96, CTXN, CTXN, 0.125f, EP_STORE, 0, 8,
        (long long)NTOK*INNER, 64, (long long)CTXN*INNER, 64,
        (long long)8*NTOK*96, (long long)NTOK*96);

    // 13. CA softmax over 77 (rounded, zero-pads to 96)
    softmax77<<<16384, 256>>>(p_sim);

    // 14. CA o = P @ v2t^T  [128 batches of (1024 x 64 x 96)] (rounded)
    gemm_mma<0><<<dim3(1,8,128), 256, SMEM_MMA>>>(p_sim, p_v, p_o, nullptr, nullptr, nullptr,
        NTOK, 96, 96, 96, INNER, 64, 64, 1.f, EP_STORE, 1, 8,
        (long long)8*NTOK*96, (long long)NTOK*96, (long long)8*64*96, (long long)64*96,
        (long long)NTOK*INNER, 64);

    // 15. h = h + (o @ ca_wo^T + ca_bo) (full precision)
    gemm_mma<0><<<dim3(4,128,1), 256, SMEM_MMA>>>(p_o, p_wr+OFF_CAO, p_h, ca_bo, nullptr, nullptr,
        MTOK, INNER, INNER, INNER, INNER, INNER, INNER, 1.f, EP_RES1, 0, 1, 0,0, 0,0, 0,0);

    // 16. out = transpose(h @ w_out^T + b_out) + x (A unrounded -> CVTA)
    gemm_mma<1><<<dim3(2,128,1), 256, SMEM_MMA>>>(p_h, p_wr+OFF_WOUT, nullptr, b_out, x, out,
        MTOK, INNER, INNER, INNER, CIN, CIN, CIN, 1.f, EP_TRANSX, 0, 1, 0,0, 0,0, 0,0);
}

// round 14
// speedup vs baseline: 1.9134x; 1.3350x over previous
#include <cuda_runtime.h>
#include <cuda_fp16.h>
#include <cstdint>
#include <math.h>

// ---------------- problem constants ----------------
#define BATCH   16
#define NTOK    1024
#define CIN     256
#define INNER   512
#define CTXN    77
#define CTXD    768
#define MTOK    (BATCH*NTOK)  // 16384
#define MCTX    (BATCH*CTXN)  // 1232

// fp16 weight scratch offsets (elements)
#define OFF_WIN  0
#define OFF_SAQ  131072
#define OFF_SAK  393216
#define OFF_SAV  655360
#define OFF_SAP  917504
#define OFF_CAQ  1179648
#define OFF_CAK  1441792
#define OFF_CAV  1835008
#define OFF_CAO  2228224
#define OFF_WOUT 2490368
#define WTOT     2621440

// ---------------- scratch (device globals; no allocation) ----------------
__device__ float g_gn1[MTOK*CIN];        // h16: gn1 out; later CA-q
__device__ float g_h  [MTOK*INNER];      // fp32 trunk
__device__ float g_hn [MTOK*INNER];      // h16: hn; later SA-P; later ctx_h
__device__ float g_q  [MTOK*INNER];      // h16: SA-q; later CA probs (24MB<=32MB)
__device__ float g_k  [MTOK*INNER];      // h16: SA-k; later shadow-h
__device__ float g_v  [MTOK*INNER];      // h16: SA-vT; later CA v2t [128][64][96]
__device__ float g_sim[16777216];        // fp32: SA sim; CA sim2 [128][1024][96]
__device__ float g_o  [MTOK*INNER];      // h16: SA-o; later CA-o
__device__ float g_k2 [MCTX*INNER];      // h16: CA k2
__device__ __half g_wh[WTOT];            // fp16 weights

// ---------------- helpers ----------------
__device__ __forceinline__ void cp16(uint32_t dst, const void* src) {
    asm volatile("cp.async.cg.shared.global [%0], [%1], 16;" :: "r"(dst), "l"(src));
}
__device__ __forceinline__ uint32_t smem_u32(const void* p) {
    uint32_t a;
    asm("{ .reg .u64 t; cvta.to.shared.u64 t, %1; cvt.u32.u64 %0, t; }" : "=r"(a) : "l"(p));
    return a;
}
__device__ __forceinline__ void mma_f16(float* c, const uint32_t* a, const uint32_t* b) {
    asm volatile("mma.sync.aligned.m16n8k16.row.col.f32.f16.f16.f32 "
                 "{%0,%1,%2,%3}, {%4,%5,%6,%7}, {%8,%9}, {%0,%1,%2,%3};"
                 : "+f"(c[0]), "+f"(c[1]), "+f"(c[2]), "+f"(c[3])
                 : "r"(a[0]), "r"(a[1]), "r"(a[2]), "r"(a[3]), "r"(b[0]), "r"(b[1]));
}
__device__ __forceinline__ void ldsm_x4(uint32_t* r, uint32_t addr) {
    asm volatile("ldmatrix.sync.aligned.x4.m8n8.shared.b16 {%0,%1,%2,%3}, [%4];"
                 : "=r"(r[0]), "=r"(r[1]), "=r"(r[2]), "=r"(r[3]) : "r"(addr));
}
__device__ __forceinline__ void ldsm_x2(uint32_t* r, uint32_t addr) {
    asm volatile("ldmatrix.sync.aligned.x2.m8n8.shared.b16 {%0,%1}, [%2];"
                 : "=r"(r[0]), "=r"(r[1]) : "r"(addr));
}

// ---------------- weight -> fp16 ----------------
__global__ void wround_kernel(const float* __restrict__ w0, const float* __restrict__ w1,
                              const float* __restrict__ w2, const float* __restrict__ w3,
                              const float* __restrict__ w4, const float* __restrict__ w5,
                              const float* __restrict__ w6, const float* __restrict__ w7,
                              const float* __restrict__ w8, const float* __restrict__ w9,
                              __half* __restrict__ dst)
{
    int i = blockIdx.x * 1024 + threadIdx.x;
    const float* s; int off;
    if      (i < OFF_SAQ)  { s = w0; off = OFF_WIN;  }
    else if (i < OFF_SAK)  { s = w1; off = OFF_SAQ;  }
    else if (i < OFF_SAV)  { s = w2; off = OFF_SAK;  }
    else if (i < OFF_SAP)  { s = w3; off = OFF_SAV;  }
    else if (i < OFF_CAQ)  { s = w4; off = OFF_SAP;  }
    else if (i < OFF_CAK)  { s = w5; off = OFF_CAQ;  }
    else if (i < OFF_CAV)  { s = w6; off = OFF_CAK;  }
    else if (i < OFF_CAO)  { s = w7; off = OFF_CAV;  }
    else if (i < OFF_WOUT) { s = w8; off = OFF_CAO;  }
    else                   { s = w9; off = OFF_WOUT; }
    dst[i] = __float2half(s[i - off]);
}

// ---------------- ctx -> fp16 (1232*768 = 946176 = 924*1024) ----------------
__global__ void ctx_h_kernel(const float* __restrict__ src, __half* __restrict__ dst)
{
    int i = blockIdx.x * 1024 + threadIdx.x;
    dst[i] = __float2half(src[i]);
}

// ---------------- GroupNorm 1 (single pass; fp16 store, token-major) ----------------
__global__ void gn1_kernel(const float* __restrict__ x, const float* __restrict__ gam,
                           const float* __restrict__ bet, __half* __restrict__ out)
{
    extern __shared__ float cache[];
    int bg = blockIdx.x;
    int b  = bg >> 5, grp = bg & 31;
    const float* xb = x + ((long)b*CIN + grp*8) * NTOK;
    __shared__ float r1[256], r2[256];
    int t = threadIdx.x;
    float s = 0.f, s2 = 0.f;
    for (int i = t; i < 8192; i += 256) {
        float v = xb[i]; cache[i] = v; s += v; s2 += v*v;
    }
    r1[t] = s; r2[t] = s2; __syncthreads();
    for (int o = 128; o > 0; o >>= 1) {
        if (t < o) { r1[t] += r1[t+o]; r2[t] += r2[t+o]; }
        __syncthreads();
    }
    float mean = r1[0] * (1.f/8192.f);
    float var  = r2[0] * (1.f/8192.f) - mean*mean;
    float rstd = rsqrtf(var + 1e-5f);
    for (int i = t; i < 8192; i += 256) {
        int c = grp*8 + (i >> 10);
        int n = i & 1023;
        float v = (cache[i] - mean) * rstd * gam[c] + bet[c];
        out[((long)b*NTOK + n)*CIN + c] = __float2half(v);
    }
}

// ---------------- GroupNorm 2 (single pass; fp16 store) ----------------
__global__ void gn2_kernel(const float* __restrict__ h, const float* __restrict__ gam,
                           const float* __restrict__ bet, __half* __restrict__ out)
{
    extern __shared__ float cache[];
    int bg = blockIdx.x;
    int b  = bg >> 5, grp = bg & 31;
    const float* hb = h + (long)b*NTOK*INNER;
    __half* ob = out + (long)b*NTOK*INNER;
    __shared__ float r1[256], r2[256];
    int t = threadIdx.x;
    float s = 0.f, s2 = 0.f;
    for (int i = t; i < 16384; i += 256) {
        int n = i >> 4, c = grp*16 + (i & 15);
        float v = hb[n*INNER + c];
        cache[i] = v; s += v; s2 += v*v;
    }
    r1[t] = s; r2[t] = s2; __syncthreads();
    for (int o = 128; o > 0; o >>= 1) {
        if (t < o) { r1[t] += r1[t+o]; r2[t] += r2[t+o]; }
        __syncthreads();
    }
    float mean = r1[0] * (1.f/16384.f);
    float var  = r2[0] * (1.f/16384.f) - mean*mean;
    float rstd = rsqrtf(var + 1e-5f);
    for (int i = t; i < 16384; i += 256) {
        int n = i >> 4, c = grp*16 + (i & 15);
        ob[n*INNER + c] = __float2half((cache[i] - mean) * rstd * gam[c] + bet[c]);
    }
}

// ---------------- SA row softmax: fp32 in -> fp16 probs ----------------
__global__ void softmax_rows(const float* __restrict__ S, __half* __restrict__ P)
{
    long long row = blockIdx.x;
    const float* p = S + row * 1024;
    __half* po = P + row * 1024;
    __shared__ float red[256];
    int t = threadIdx.x;
    float v[4];
    float mx = -1e30f;
    #pragma unroll
    for (int i = 0; i < 4; i++) { v[i] = p[t + i*256]; mx = fmaxf(mx, v[i]); }
    red[t] = mx; __syncthreads();
    for (int o = 128; o > 0; o >>= 1) {
        if (t < o) red[t] = fmaxf(red[t], red[t+o]);
        __syncthreads();
    }
    mx = red[0]; __syncthreads();
    float sum = 0.f;
    #pragma unroll
    for (int i = 0; i < 4; i++) { v[i] = __expf(v[i] - mx); sum += v[i]; }
    red[t] = sum; __syncthreads();
    for (int o = 128; o > 0; o >>= 1) {
        if (t < o) red[t] += red[t+o];
        __syncthreads();
    }
    float inv = 1.f / red[0];
    #pragma unroll
    for (int i = 0; i < 4; i++) po[t + i*256] = __float2half(v[i] * inv);
}

// ---------------- CA softmax: fp32 in (rows x 96, 77 valid) -> fp16 out ----------------
__global__ void softmax77(const float* __restrict__ S, __half* __restrict__ P)
{
    int warp = (blockIdx.x * 256 + threadIdx.x) >> 5;
    int l = threadIdx.x & 31;
    const float* p = S + (long long)warp * 96;
    __half* po = P + (long long)warp * 96;
    float v0 = p[l];
    float v1 = p[l + 32];
    float v2 = (l + 64 < 77) ? p[l + 64] : -1e30f;
    float mx = fmaxf(v0, fmaxf(v1, v2));
    #pragma unroll
    for (int off = 16; off > 0; off >>= 1)
        mx = fmaxf(mx, __shfl_xor_sync(0xFFFFFFFFu, mx, off));
    float e0 = __expf(v0 - mx), e1 = __expf(v1 - mx);
    float e2 = (l + 64 < 77) ? __expf(v2 - mx) : 0.f;
    float sum = e0 + e1 + e2;
    #pragma unroll
    for (int off = 16; off > 0; off >>= 1)
        sum += __shfl_xor_sync(0xFFFFFFFFu, sum, off);
    float inv = 1.f / sum;
    po[l]      = __float2half(e0 * inv);
    po[l + 32] = __float2half(e1 * inv);
    po[l + 64] = __float2half((l + 64 < 77) ? e2 * inv : 0.f);
}

// =======================================================================
// fp16 mma.sync NT GEMM: C = alpha * A[M,K] @ W[N,K]^T (+ epilogues)
// 128x128 CTA, 8 warps x (64x32), m16n8k16, 3-stage cp.async, ldmatrix.
// smem rows: 32 halfs + 8 pad = 80 B (conflict-free, 16B-aligned).
// =======================================================================
#define EP_STORE    0   // fp32 store (C float)
#define EP_RES2     1   // C(fp32) = 2C + acc; shadow fp16 via outx
#define EP_RES1     2   // C(fp32) = C + acc + bias; shadow fp16 via outx
#define EP_TRANSX   3   // fp32 transposed +x final store
#define EP_STOREH   4   // fp16 store
#define EP_STORETH  5   // fp16 transposed store (SA vT)
#define EP_STORECVH 6   // fp16 CA v2t store

#define BK     32
#define ROWB   80                      // bytes per smem row
#define TILEB  (128*ROWB)              // 10240 B per tile
#define STAGEB (2*TILEB)               // 20480 B
#define NSTAGE 3
#define SMEM_MMA (NSTAGE*STAGEB)       // 61440 B -> 2 CTAs/SM easily

__global__ __launch_bounds__(256, 2)
void gemm_h(const __half* __restrict__ A, const __half* __restrict__ W,
            void* __restrict__ Cv, const float* __restrict__ bias,
            const float* __restrict__ xin, void* __restrict__ outx,
            int M, int K, int lda, int ldw, int ldc,
            int wrowmax, int nvalid, float alpha, int mode,
            int HZ, long long sAb, long long sAh,
            long long sWb, long long sWh, long long sCb, long long sCh)
{
    extern __shared__ char smem[];
    float*  Cf = (float*)Cv;
    __half* Ch = (__half*)Cv;
    {
        int z = blockIdx.z;
        int zb = z, zh = 0;
        if (HZ > 1) { zb = z / HZ; zh = z - zb * HZ; }
        A  += zb*sAb + zh*sAh;
        W  += zb*sWb + zh*sWh;
        Cf += zb*sCb + zh*sCh;
        Ch += zb*sCb + zh*sCh;
    }

    const int m0 = blockIdx.y * 128, n0 = blockIdx.x * 128;
    const int tid = threadIdx.x;
    const int wid = tid >> 5, lane = tid & 31;
    const int wm = wid & 1, wn = wid >> 1;      // 2x4 warp grid, 64x32 tiles
    const int rowmax = M - m0;
    const uint32_t sbase = smem_u32(smem);

    const __half* Ag = A + (long long)m0 * lda;

    float acc[4][4][4];
    #pragma unroll
    for (int i = 0; i < 4; i++)
        #pragma unroll
        for (int j = 0; j < 4; j++)
            #pragma unroll
            for (int r = 0; r < 4; r++) acc[i][j][r] = 0.f;

    const int nch = K >> 5;

    auto load_tiles = [&](int buf, int c) {
        uint32_t sA = sbase + buf * STAGEB;
        uint32_t sW = sA + TILEB;
        const __half* Agk = Ag + c * BK;
        #pragma unroll
        for (int i = 0; i < 2; i++) {
            int f = tid + 256 * i;            // 512 chunks: 128 rows x 4x16B
            int r = f >> 2, q = f & 3;
            int ra = (r < rowmax) ? r : (rowmax - 1);
            cp16(sA + r * ROWB + q * 16, Agk + (long long)ra * lda + q * 8);
        }
        #pragma unroll
        for (int i = 0; i < 2; i++) {
            int f = tid + 256 * i;
            int r = f >> 2, q = f & 3;
            int rw = (n0 + r < wrowmax) ? (n0 + r) : (wrowmax - 1);
            cp16(sW + r * ROWB + q * 16, W + (long long)rw * ldw + c * BK + q * 8);
        }
        asm volatile("cp.async.commit_group;" ::: "memory");
    };

    load_tiles(0, 0);
    load_tiles(1, 1);

    const int frow = lane >> 2;
    const int fcol = lane & 3;

    // ldmatrix per-lane addresses (bytes)
    // A x4: mats {m0-7,k0-7}(lanes0-7), {m8-15,k0-7}(8-15), {m0-7,k8-15}(16-23), {m8-15,k8-15}(24-31)
    const uint32_t aoff = (uint32_t)(wm * 64 + ((lane >> 3) & 1) * 8 + (lane & 7)) * ROWB
                        + (uint32_t)(lane >> 4) * 16;
    // B x2: mats {n0-7,k0-7}(lanes0-7), {n0-7,k8-15}(8-15)
    const uint32_t boff = (uint32_t)(wn * 32 + (lane & 7)) * ROWB
                        + (uint32_t)((lane >> 3) & 1) * 16;

    int buf = 0, lb = 2;
    for (int c = 0; c < nch; c++) {
        asm volatile("cp.async.wait_group 1;" ::: "memory");
        __syncthreads();
        if (c + 2 < nch) {
            load_tiles(lb, c + 2);
        } else {
            asm volatile("cp.async.commit_group;" ::: "memory");
        }

        const uint32_t sA = sbase + buf * STAGEB;
        const uint32_t sW = sA + TILEB;

        #pragma unroll
        for (int kk = 0; kk < 2; kk++) {
            const uint32_t kbB = kk * 32;     // 16 halfs = 32 bytes
            uint32_t a[4][4], b[4][2];
            #pragma unroll
            for (int mf = 0; mf < 4; mf++)
                ldsm_x4(a[mf], sA + aoff + (uint32_t)(mf * 16 * ROWB) + kbB);
            #pragma unroll
            for (int nf = 0; nf < 4; nf++)
                ldsm_x2(b[nf], sW + boff + (uint32_t)(nf * 8 * ROWB) + kbB);
            #pragma unroll
            for (int mf = 0; mf < 4; mf++)
                #pragma unroll
                for (int nf = 0; nf < 4; nf++)
                    mma_f16(acc[mf][nf], a[mf], b[nf]);
        }
        buf = (buf == NSTAGE-1) ? 0 : buf + 1;
        lb  = (lb  == NSTAGE-1) ? 0 : lb  + 1;
    }

    // ---- epilogue ----
    #pragma unroll
    for (int mf = 0; mf < 4; mf++) {
        #pragma unroll
        for (int nf = 0; nf < 4; nf++) {
            int rg  = m0 + wm * 64 + mf * 16 + frow;
            int cg  = n0 + wn * 32 + nf * 8 + 2 * fcol;
            bool g0 = cg < nvalid, g1 = cg + 1 < nvalid;
            #pragma unroll
            for (int half2 = 0; half2 < 2; half2++) {
                int row = rg + half2 * 8;
                if (row >= M) continue;
                float v0 = alpha * acc[mf][nf][half2 * 2 + 0];
                float v1 = alpha * acc[mf][nf][half2 * 2 + 1];
                if (bias) {
                    if (g0) v0 += bias[cg];
                    if (g1) v1 += bias[cg + 1];
                }
                if (mode == EP_STORE) {
                    float* cp = Cf + (long long)row * ldc + cg;
                    if (g0) cp[0] = v0;
                    if (g1) cp[1] = v1;
                } else if (mode == EP_STOREH) {
                    __half* cp = Ch + (long long)row * ldc + cg;
                    if (g0) cp[0] = __float2half(v0);
                    if (g1) cp[1] = __float2half(v1);
                } else if (mode == EP_RES2 || mode == EP_RES1) {
                    float* cp = Cf + (long long)row * ldc + cg;
                    float r0 = (mode == EP_RES2) ? 2.f*cp[0] + v0 : cp[0] + v0;
                    float r1 = (mode == EP_RES2) ? 2.f*cp[1] + v1 : cp[1] + v1;
                    cp[0] = r0; cp[1] = r1;
                    __half* sh = (__half*)outx + (long long)row * ldc + cg;
                    sh[0] = __float2half(r0);
                    sh[1] = __float2half(r1);
                } else if (mode == EP_TRANSX) {
                    int bb = row >> 10, n = row & 1023;
                    long long o0 = (((long long)bb * CIN + cg) << 10) + n;
                    float* ox = (float*)outx;
                    if (g0) ox[o0]        = v0 + xin[o0];
                    if (g1) ox[o0 + 1024] = v1 + xin[o0 + 1024];
                } else if (mode == EP_STORETH) {
                    int bb = row >> 10, n = row & 1023;
                    long long o0 = (((long long)bb * INNER + cg) << 10) + n;
                    Ch[o0]        = __float2half(v0);
                    Ch[o0 + 1024] = __float2half(v1);
                } else { // EP_STORECVH: v2t[(b*8+h)*64*96 + d*96 + j]; row=b*77+j, col=h*64+d
                    int bb = row / 77, j = row - bb * 77;
                    int h0 = cg >> 6, d0 = cg & 63;
                    int h1 = (cg + 1) >> 6, d1 = (cg + 1) & 63;
                    Ch[((long long)(bb * 8 + h0) * 64 + d0) * 96 + j] = __float2half(v0);
                    Ch[((long long)(bb * 8 + h1) * 64 + d1) * 96 + j] = __float2half(v1);
                }
            }
        }
    }
}

// =======================================================================
// host launch
// =======================================================================
extern "C" void kernel_launch(void* const* d_in, const int* in_sizes, int n_in,
                              void* d_out, int out_size)
{
    const float* x      = (const float*)d_in[0];
    const float* ctx    = (const float*)d_in[1];
    const float* gn1_g  = (const float*)d_in[2];
    const float* gn1_b  = (const float*)d_in[3];
    const float* w_in   = (const float*)d_in[4];
    const float* b_in   = (const float*)d_in[5];
    const float* sa_wk  = (const float*)d_in[6];
    const float* sa_wq  = (const float*)d_in[7];
    const float* sa_wv  = (const float*)d_in[8];
    const float* sa_wp  = (const float*)d_in[9];
    const float* sa_gng = (const float*)d_in[10];
    const float* sa_gnb = (const float*)d_in[11];
    const float* ca_wq  = (const float*)d_in[12];
    const float* ca_wk  = (const float*)d_in[13];
    const float* ca_wv  = (const float*)d_in[14];
    const float* ca_wo  = (const float*)d_in[15];
    const float* ca_bo  = (const float*)d_in[16];
    const float* w_out  = (const float*)d_in[17];
    const float* b_out  = (const float*)d_in[18];
    float* out = (float*)d_out;

    float *p_gn1, *p_h, *p_hn, *p_q, *p_k, *p_v, *p_sim, *p_o, *p_k2;
    __half* p_wh;
    cudaGetSymbolAddress((void**)&p_gn1, g_gn1);
    cudaGetSymbolAddress((void**)&p_h,   g_h);
    cudaGetSymbolAddress((void**)&p_hn,  g_hn);
    cudaGetSymbolAddress((void**)&p_q,   g_q);
    cudaGetSymbolAddress((void**)&p_k,   g_k);
    cudaGetSymbolAddress((void**)&p_v,   g_v);
    cudaGetSymbolAddress((void**)&p_sim, g_sim);
    cudaGetSymbolAddress((void**)&p_o,   g_o);
    cudaGetSymbolAddress((void**)&p_k2,  g_k2);
    cudaGetSymbolAddress((void**)&p_wh,  g_wh);

    __half* h_gn1 = (__half*)p_gn1;   // gn1 out; later CA-q
    __half* h_hn  = (__half*)p_hn;    // hn; later SA-P; later ctx_h
    __half* h_q   = (__half*)p_q;     // SA-q; later CA probs
    __half* h_k   = (__half*)p_k;     // SA-k; later shadow-h
    __half* h_v   = (__half*)p_v;     // SA-vT; later CA v2t
    __half* h_o   = (__half*)p_o;     // SA-o; later CA-o
    __half* h_k2  = (__half*)p_k2;    // CA k2

    cudaFuncSetAttribute(gemm_h,     cudaFuncAttributeMaxDynamicSharedMemorySize, SMEM_MMA);
    cudaFuncSetAttribute(gn1_kernel, cudaFuncAttributeMaxDynamicSharedMemorySize, 32768);
    cudaFuncSetAttribute(gn2_kernel, cudaFuncAttributeMaxDynamicSharedMemorySize, 65536);

    const float simScale = 0.044194173824159216f; // 512^-0.5

    // 0. weights -> fp16
    wround_kernel<<<WTOT/1024, 1024>>>(w_in, sa_wq, sa_wk, sa_wv, sa_wp,
                                       ca_wq, ca_wk, ca_wv, ca_wo, w_out, p_wh);

    // 1. GroupNorm1 -> token-major fp16
    gn1_kernel<<<BATCH*32, 256, 32768>>>(x, gn1_g, gn1_b, h_gn1);

    // 2. conv_in: h(fp32) = gn1 @ w_in^T + b_in
    gemm_h<<<dim3(4,128,1), 256, SMEM_MMA>>>(h_gn1, p_wh+OFF_WIN, p_h, b_in, nullptr, nullptr,
        MTOK, CIN, CIN, CIN, INNER, INNER, INNER, 1.f, EP_STORE, 1, 0,0, 0,0, 0,0);

    // 3. SA groupnorm -> fp16 hn
    gn2_kernel<<<BATCH*32, 256, 65536>>>(p_h, sa_gng, sa_gnb, h_hn);

    // 4. q/k/v projections (fp16; v stored transposed per batch)
    gemm_h<<<dim3(4,128,1), 256, SMEM_MMA>>>(h_hn, p_wh+OFF_SAQ, h_q, nullptr, nullptr, nullptr,
        MTOK, INNER, INNER, INNER, INNER, INNER, INNER, 1.f, EP_STOREH, 1, 0,0, 0,0, 0,0);
    gemm_h<<<dim3(4,128,1), 256, SMEM_MMA>>>(h_hn, p_wh+OFF_SAK, h_k, nullptr, nullptr, nullptr,
        MTOK, INNER, INNER, INNER, INNER, INNER, INNER, 1.f, EP_STOREH, 1, 0,0, 0,0, 0,0);
    gemm_h<<<dim3(4,128,1), 256, SMEM_MMA>>>(h_hn, p_wh+OFF_SAV, h_v, nullptr, nullptr, nullptr,
        MTOK, INNER, INNER, INNER, INNER, INNER, INNER, 1.f, EP_STORETH, 1, 0,0, 0,0, 0,0);

    // 5. sim(fp32) = scale * q @ k^T (batched)
    gemm_h<<<dim3(8,8,BATCH), 256, SMEM_MMA>>>(h_q, h_k, p_sim, nullptr, nullptr, nullptr,
        NTOK, INNER, INNER, INNER, NTOK, NTOK, NTOK, simScale, EP_STORE, 1,
        (long long)NTOK*INNER, 0, (long long)NTOK*INNER, 0, (long long)NTOK*NTOK, 0);

    // 6. SA softmax: fp32 -> fp16 P (into hn)
    softmax_rows<<<MTOK, 256>>>(p_sim, h_hn);

    // 7. o(fp16) = P @ vT^T (batched)
    gemm_h<<<dim3(4,8,BATCH), 256, SMEM_MMA>>>(h_hn, h_v, h_o, nullptr, nullptr, nullptr,
        NTOK, NTOK, NTOK, NTOK, INNER, INNER, INNER, 1.f, EP_STOREH, 1,
        (long long)NTOK*NTOK, 0, (long long)INNER*NTOK, 0, (long long)NTOK*INNER, 0);

    // 8. h = 2h + o @ sa_wp^T (fp32) + shadow fp16 -> h_k
    gemm_h<<<dim3(4,128,1), 256, SMEM_MMA>>>(h_o, p_wh+OFF_SAP, p_h, nullptr, nullptr, h_k,
        MTOK, INNER, INNER, INNER, INNER, INNER, INNER, 1.f, EP_RES2, 1, 0,0, 0,0, 0,0);

    // 9. CA q(fp16) = shadow-h @ ca_wq^T -> h_gn1
    gemm_h<<<dim3(4,128,1), 256, SMEM_MMA>>>(h_k, p_wh+OFF_CAQ, h_gn1, nullptr, nullptr, nullptr,
        MTOK, INNER, INNER, INNER, INNER, INNER, INNER, 1.f, EP_STOREH, 1, 0,0, 0,0, 0,0);

    // 9.5 ctx -> fp16 (into hn; P dead)
    ctx_h_kernel<<<(MCTX*CTXD)/1024, 1024>>>(ctx, h_hn);

    // 10/11. CA k2(fp16), v2t(fp16)
    gemm_h<<<dim3(4,10,1), 256, SMEM_MMA>>>(h_hn, p_wh+OFF_CAK, h_k2, nullptr, nullptr, nullptr,
        MCTX, CTXD, CTXD, CTXD, INNER, INNER, INNER, 1.f, EP_STOREH, 1, 0,0, 0,0, 0,0);
    gemm_h<<<dim3(4,10,1), 256, SMEM_MMA>>>(h_hn, p_wh+OFF_CAV, h_v, nullptr, nullptr, nullptr,
        MCTX, CTXD, CTXD, CTXD, INNER, INNER, INNER, 1.f, EP_STORECVH, 1, 0,0, 0,0, 0,0);

    // 12. CA sim2(fp32) = 0.125 * Q_head @ K2_head^T [128 batches, K=64]
    gemm_h<<<dim3(1,8,128), 256, SMEM_MMA>>>(h_gn1, h_k2, p_sim, nullptr, nullptr, nullptr,
        NTOK, 64, INNER, INNER, 96, CTXN, CTXN, 0.125f, EP_STORE, 8,
        (long long)NTOK*INNER, 64, (long long)CTXN*INNER, 64,
        (long long)8*NTOK*96, (long long)NTOK*96);

    // 13. CA softmax -> fp16 probs (into h_q; SA-q dead)
    softmax77<<<16384, 256>>>(p_sim, h_q);

    // 14. CA o(fp16) = P @ v2t^T [128 batches, K=96]
    gemm_h<<<dim3(1,8,128), 256, SMEM_MMA>>>(h_q, h_v, h_o, nullptr, nullptr, nullptr,
        NTOK, 96, 96, 96, INNER, 64, 64, 1.f, EP_STOREH, 8,
        (long long)8*NTOK*96, (long long)NTOK*96, (long long)8*64*96, (long long)64*96,
        (long long)NTOK*INNER, 64);

    // 15. h = h + (o @ ca_wo^T + ca_bo) (fp32) + shadow fp16 -> h_k
    gemm_h<<<dim3(4,128,1), 256, SMEM_MMA>>>(h_o, p_wh+OFF_CAO, p_h, ca_bo, nullptr, h_k,
        MTOK, INNER, INNER, INNER, INNER, INNER, INNER, 1.f, EP_RES1, 1, 0,0, 0,0, 0,0);

    // 16. out = transpose(shadow-h @ w_out^T + b_out) + x
    gemm_h<<<dim3(2,128,1), 256, SMEM_MMA>>>(h_k, p_wh+OFF_WOUT, nullptr, b_out, x, out,
        MTOK, INNER, INNER, INNER, CIN, CIN, CIN, 1.f, EP_TRANSX, 1, 0,0, 0,0, 0,0);
}